// round 6
// baseline (speedup 1.0000x reference)
#include <cuda_runtime.h>
#include <cuda_bf16.h>
#include <cstdint>

__device__ __forceinline__ float2 cmul(float2 a, float2 b) {
    return make_float2(a.x * b.x - a.y * b.y, a.x * b.y + a.y * b.x);
}
__device__ __forceinline__ float2 cadd(float2 a, float2 b) {
    return make_float2(a.x + b.x, a.y + b.y);
}

// One block per (bs, set). Produces 4096 fp32 outputs (16 KB) per block.
// Qubit q occupies bit (11-q) of the state index (qubit 0 = MSB).
// state[i] = Re( L[i>>6] * R[i&63] ), where L/R are partial tensor products
// over qubits 0..5 / 6..11 of the per-qubit rotated 2-vectors.
__global__ __launch_bounds__(256, 8)
void vqc_state_kernel(const float* __restrict__ angles,
                      const float* __restrict__ tQ,
                      const float* __restrict__ tK,
                      const float* __restrict__ tV,
                      float* __restrict__ out,
                      int BS, int n_layers) {
    const int bs  = blockIdx.x;
    const int w   = blockIdx.y;
    const int tid = threadIdx.x;

    __shared__ float2 v[12][2];   // per-qubit rotated state (complex 2-vector)
    __shared__ float2 Ls[64];     // partial product over qubits 0..5 (high bits)
    __shared__ float2 Rs[64];     // partial product over qubits 6..11 (low bits)

    if (tid < 12) {
        // --- accumulate this qubit's 2x2 unitary over layers:  U <- Ul @ U ---
        // Ul = Rz(p2) Ry(p1) Rz(p0), p_i = theta_i / 2
        //    = [[c1 e^{-i(p0+p2)}, -s1 e^{+i(p0-p2)}],
        //       [s1 e^{-i(p0-p2)},  c1 e^{+i(p0+p2)}]]
        const float* th = (w == 0) ? tQ : (w == 1) ? tK : tV;
        float2 U00 = {1.f, 0.f}, U01 = {0.f, 0.f};
        float2 U10 = {0.f, 0.f}, U11 = {1.f, 0.f};
        for (int l = 0; l < n_layers; ++l) {
            const float* tl = th + (l * 12 + tid) * 3;
            float p0 = 0.5f * tl[0];
            float p1 = 0.5f * tl[1];
            float p2 = 0.5f * tl[2];
            float c1, s1, ca, sa, cb, sb;
            sincosf(p1, &s1, &c1);
            sincosf(p0 + p2, &sa, &ca);
            sincosf(p0 - p2, &sb, &cb);
            float2 A00 = { c1 * ca, -c1 * sa};
            float2 A01 = {-s1 * cb, -s1 * sb};
            float2 A10 = { s1 * cb, -s1 * sb};
            float2 A11 = { c1 * ca,  c1 * sa};
            float2 n00 = cadd(cmul(A00, U00), cmul(A01, U10));
            float2 n01 = cadd(cmul(A00, U01), cmul(A01, U11));
            float2 n10 = cadd(cmul(A10, U00), cmul(A11, U10));
            float2 n11 = cadd(cmul(A10, U01), cmul(A11, U11));
            U00 = n00; U01 = n01; U10 = n10; U11 = n11;
        }
        // --- apply to the encoded angle state [cos(a/2), sin(a/2)] ---
        float a = angles[bs * 12 + tid];
        float c, s;
        sincosf(0.5f * a, &s, &c);
        v[tid][0] = make_float2(U00.x * c + U01.x * s, U00.y * c + U01.y * s);
        v[tid][1] = make_float2(U10.x * c + U11.x * s, U10.y * c + U11.y * s);
    }
    __syncthreads();

    if (tid < 128) {
        int half  = tid >> 6;         // 0: L (qubits 0..5), 1: R (qubits 6..11)
        int h     = tid & 63;
        int qbase = half * 6;
        float2 p = v[qbase][(h >> 5) & 1];
        #pragma unroll
        for (int j = 1; j < 6; ++j)
            p = cmul(p, v[qbase + j][(h >> (5 - j)) & 1]);
        if (half == 0) Ls[h] = p; else Rs[h] = p;
    }
    __syncthreads();

    // Each thread stores 4 float4's (16 outputs). The low-6-bit (R) index of a
    // thread's quad is invariant across iterations: (it*256+tid)*4 & 63 == (tid*4)&63.
    const int lo = (tid << 2) & 63;
    const float2 r0 = Rs[lo], r1 = Rs[lo + 1], r2 = Rs[lo + 2], r3 = Rs[lo + 3];

    float4* o4 = reinterpret_cast<float4*>(out + ((size_t)w * BS + bs) * 4096);
    #pragma unroll
    for (int it = 0; it < 4; ++it) {
        int idx4 = it * 256 + tid;
        float2 Lh = Ls[(idx4 << 2) >> 6];   // = it*16 + (tid>>4): warp-broadcast LDS
        float4 r;
        r.x = Lh.x * r0.x - Lh.y * r0.y;
        r.y = Lh.x * r1.x - Lh.y * r1.y;
        r.z = Lh.x * r2.x - Lh.y * r2.y;
        r.w = Lh.x * r3.x - Lh.y * r3.y;
        o4[idx4] = r;
    }
}

extern "C" void kernel_launch(void* const* d_in, const int* in_sizes, int n_in,
                              void* d_out, int out_size) {
    const float* angles = (const float*)d_in[0];
    const float* tQ     = (const float*)d_in[1];
    const float* tK     = (const float*)d_in[2];
    const float* tV     = (const float*)d_in[3];
    float* out          = (float*)d_out;

    const int NQ = 12;
    const int BS = in_sizes[0] / NQ;          // B*S = 4096
    const int L  = in_sizes[1] / (NQ * 3);    // 4 layers

    dim3 grid(BS, 3);
    vqc_state_kernel<<<grid, 256>>>(angles, tQ, tK, tV, out, BS, L);
}

// round 7
// speedup vs baseline: 1.1672x; 1.1672x over previous
#include <cuda_runtime.h>
#include <cuda_bf16.h>
#include <cstdint>

#define ITEMS 4

__device__ __forceinline__ float2 cmul(float2 a, float2 b) {
    return make_float2(a.x * b.x - a.y * b.y, a.x * b.y + a.y * b.x);
}
__device__ __forceinline__ float2 cadd(float2 a, float2 b) {
    return make_float2(a.x + b.x, a.y + b.y);
}

// One block per (4 bs items, set). Produces 4*4096 fp32 outputs (64 KB) per block.
// Qubit q occupies bit (11-q) of the state index (qubit 0 = MSB).
// state[i] = Re( L[i>>6] * R[i&63] ), L/R = partial tensor products over
// qubits 0..5 / 6..11 of the per-qubit rotated 2-vectors.
__global__ __launch_bounds__(256, 8)
void vqc_state_kernel(const float* __restrict__ angles,
                      const float* __restrict__ tQ,
                      const float* __restrict__ tK,
                      const float* __restrict__ tV,
                      float* __restrict__ out,
                      int BS, int n_layers) {
    const int ib  = blockIdx.x * ITEMS;   // first bs item of this block
    const int w   = blockIdx.y;           // which theta set (Q/K/V)
    const int tid = threadIdx.x;

    __shared__ float2 v[ITEMS][12][2];    // per-(item,qubit) rotated 2-vector
    __shared__ float2 Ls[ITEMS][64];      // partial product, qubits 0..5 (high bits)
    __shared__ float2 Rs[ITEMS][64];      // partial product, qubits 6..11 (low bits)

    // ---- Phase 1: 48 threads = (item, qubit). Unitary accum + angle rotation ----
    if (tid < 12 * ITEMS) {
        const int item = tid / 12;
        const int q    = tid % 12;
        const float* th = (w == 0) ? tQ : (w == 1) ? tK : tV;

        // U <- Ul @ U over layers;  Ul = Rz(p2) Ry(p1) Rz(p0), p_i = theta_i/2
        //   = [[c1 e^{-i(p0+p2)}, -s1 e^{+i(p0-p2)}],
        //      [s1 e^{-i(p0-p2)},  c1 e^{+i(p0+p2)}]]
        float2 U00 = {1.f, 0.f}, U01 = {0.f, 0.f};
        float2 U10 = {0.f, 0.f}, U11 = {1.f, 0.f};
        for (int l = 0; l < n_layers; ++l) {
            const float* tl = th + (l * 12 + q) * 3;
            float p0 = 0.5f * tl[0];
            float p1 = 0.5f * tl[1];
            float p2 = 0.5f * tl[2];
            float c1, s1, ca, sa, cb, sb;
            sincosf(p1, &s1, &c1);
            sincosf(p0 + p2, &sa, &ca);
            sincosf(p0 - p2, &sb, &cb);
            float2 A00 = { c1 * ca, -c1 * sa};
            float2 A01 = {-s1 * cb, -s1 * sb};
            float2 A10 = { s1 * cb, -s1 * sb};
            float2 A11 = { c1 * ca,  c1 * sa};
            float2 n00 = cadd(cmul(A00, U00), cmul(A01, U10));
            float2 n01 = cadd(cmul(A00, U01), cmul(A01, U11));
            float2 n10 = cadd(cmul(A10, U00), cmul(A11, U10));
            float2 n11 = cadd(cmul(A10, U01), cmul(A11, U11));
            U00 = n00; U01 = n01; U10 = n10; U11 = n11;
        }
        float a = angles[(ib + item) * 12 + q];
        float c, s;
        sincosf(0.5f * a, &s, &c);
        v[item][q][0] = make_float2(U00.x * c + U01.x * s, U00.y * c + U01.y * s);
        v[item][q][1] = make_float2(U10.x * c + U11.x * s, U10.y * c + U11.y * s);
    }
    __syncthreads();

    // ---- Phase 2: 512 partial-product tasks, 2 per thread ----
    #pragma unroll
    for (int tt = 0; tt < 2; ++tt) {
        int t     = tid + tt * 256;       // 0..511
        int item  = t >> 7;
        int rest  = t & 127;
        int half  = rest >> 6;            // 0: L (qubits 0..5), 1: R (qubits 6..11)
        int h     = rest & 63;
        int qbase = half * 6;
        float2 p = v[item][qbase][(h >> 5) & 1];
        #pragma unroll
        for (int j = 1; j < 6; ++j)
            p = cmul(p, v[item][qbase + j][(h >> (5 - j)) & 1]);
        if (half == 0) Ls[item][h] = p; else Rs[item][h] = p;
    }
    __syncthreads();

    // ---- Phase 3: stores. Per item: 4 float4 per thread (1024 float4/item).
    // Low-6-bit (R) index of a thread's quad is invariant: (it*256+tid)*4 & 63 == (tid*4)&63
    const int lo = (tid << 2) & 63;
    #pragma unroll
    for (int item = 0; item < ITEMS; ++item) {
        const float2 r0 = Rs[item][lo],     r1 = Rs[item][lo + 1];
        const float2 r2 = Rs[item][lo + 2], r3 = Rs[item][lo + 3];
        float4* o4 = reinterpret_cast<float4*>(out + ((size_t)w * BS + ib + item) * 4096);
        #pragma unroll
        for (int it = 0; it < 4; ++it) {
            int idx4 = it * 256 + tid;
            float2 Lh = Ls[item][idx4 >> 4];   // warp-broadcast LDS
            float4 r;
            r.x = Lh.x * r0.x - Lh.y * r0.y;
            r.y = Lh.x * r1.x - Lh.y * r1.y;
            r.z = Lh.x * r2.x - Lh.y * r2.y;
            r.w = Lh.x * r3.x - Lh.y * r3.y;
            o4[idx4] = r;
        }
    }
}

extern "C" void kernel_launch(void* const* d_in, const int* in_sizes, int n_in,
                              void* d_out, int out_size) {
    const float* angles = (const float*)d_in[0];
    const float* tQ     = (const float*)d_in[1];
    const float* tK     = (const float*)d_in[2];
    const float* tV     = (const float*)d_in[3];
    float* out          = (float*)d_out;

    const int NQ = 12;
    const int BS = in_sizes[0] / NQ;          // B*S = 4096
    const int L  = in_sizes[1] / (NQ * 3);    // 4 layers

    dim3 grid(BS / ITEMS, 3);
    vqc_state_kernel<<<grid, 256>>>(angles, tQ, tK, tV, out, BS, L);
}

// round 8
// speedup vs baseline: 1.2109x; 1.0374x over previous
#include <cuda_runtime.h>
#include <cuda_bf16.h>
#include <cstdint>

__device__ __forceinline__ float2 cmul(float2 a, float2 b) {
    return make_float2(a.x * b.x - a.y * b.y, a.x * b.y + a.y * b.x);
}
__device__ __forceinline__ float2 cadd(float2 a, float2 b) {
    return make_float2(a.x + b.x, a.y + b.y);
}

// Warp-autonomous: global warp g produces item g = w*BS + bs (4096 fp32 = 16 KB).
// Qubit q occupies bit (11-q) of the state index.
// state[i] = Re( L[i>>6] * R[i&63] ); L over qubits 0..5, R over qubits 6..11.
// No shared memory, no __syncthreads — all cross-lane traffic via shfl.
__global__ __launch_bounds__(256, 4)
void vqc_warp_kernel(const float* __restrict__ angles,
                     const float* __restrict__ tQ,
                     const float* __restrict__ tK,
                     const float* __restrict__ tV,
                     float* __restrict__ out,
                     int BS, int n_layers) {
    const unsigned FULL = 0xFFFFFFFFu;
    const int g  = blockIdx.x * 8 + (threadIdx.x >> 5);   // item id
    const int ln = threadIdx.x & 31;
    const int w  = g / BS;
    const int bs = g - w * BS;

    // ---------- Phase A: lanes 0..11 build this item's per-qubit 2-vectors ----------
    float2 v0 = {0.f, 0.f}, v1 = {0.f, 0.f};   // v[q][0], v[q][1] for q = lane
    if (ln < 12) {
        const int q = ln;
        const float* th = (w == 0) ? tQ : (w == 1) ? tK : tV;
        // U <- Ul @ U;  Ul = Rz(p2) Ry(p1) Rz(p0), p_i = theta_i/2
        //   = [[c1 e^{-i(p0+p2)}, -s1 e^{+i(p0-p2)}],
        //      [s1 e^{-i(p0-p2)},  c1 e^{+i(p0+p2)}]]
        float2 U00 = {1.f, 0.f}, U01 = {0.f, 0.f};
        float2 U10 = {0.f, 0.f}, U11 = {1.f, 0.f};
        for (int l = 0; l < n_layers; ++l) {
            const float* tl = th + (l * 12 + q) * 3;
            float p0 = 0.5f * tl[0];
            float p1 = 0.5f * tl[1];
            float p2 = 0.5f * tl[2];
            float c1, s1, ca, sa, cb, sb;
            sincosf(p1, &s1, &c1);
            sincosf(p0 + p2, &sa, &ca);
            sincosf(p0 - p2, &sb, &cb);
            float2 A00 = { c1 * ca, -c1 * sa};
            float2 A01 = {-s1 * cb, -s1 * sb};
            float2 A10 = { s1 * cb, -s1 * sb};
            float2 A11 = { c1 * ca,  c1 * sa};
            float2 n00 = cadd(cmul(A00, U00), cmul(A01, U10));
            float2 n01 = cadd(cmul(A00, U01), cmul(A01, U11));
            float2 n10 = cadd(cmul(A10, U00), cmul(A11, U10));
            float2 n11 = cadd(cmul(A10, U01), cmul(A11, U11));
            U00 = n00; U01 = n01; U10 = n10; U11 = n11;
        }
        float a = angles[bs * 12 + q];
        float c, s;
        sincosf(0.5f * a, &s, &c);
        v0 = make_float2(U00.x * c + U01.x * s, U00.y * c + U01.y * s);
        v1 = make_float2(U10.x * c + U11.x * s, U10.y * c + U11.y * s);
    }

    // ---------- Phase B: distributed partial products via shfl ----------
    // Lane ln holds L[ln], L[ln+32], R[ln], R[ln+32].
    float2 L0, L1, R0, R1;
    {
        float2 a0[6], a1[6];   // broadcast of v[j][0], v[j][1]
        // L over qubits 0..5
        #pragma unroll
        for (int j = 0; j < 6; ++j) {
            a0[j].x = __shfl_sync(FULL, v0.x, j);
            a0[j].y = __shfl_sync(FULL, v0.y, j);
            a1[j].x = __shfl_sync(FULL, v1.x, j);
            a1[j].y = __shfl_sync(FULL, v1.y, j);
        }
        #pragma unroll
        for (int hh = 0; hh < 2; ++hh) {
            int h = ln + hh * 32;
            float2 p = ((h >> 5) & 1) ? a1[0] : a0[0];
            #pragma unroll
            for (int j = 1; j < 6; ++j)
                p = cmul(p, ((h >> (5 - j)) & 1) ? a1[j] : a0[j]);
            if (hh == 0) L0 = p; else L1 = p;
        }
        // R over qubits 6..11
        #pragma unroll
        for (int j = 0; j < 6; ++j) {
            a0[j].x = __shfl_sync(FULL, v0.x, 6 + j);
            a0[j].y = __shfl_sync(FULL, v0.y, 6 + j);
            a1[j].x = __shfl_sync(FULL, v1.x, 6 + j);
            a1[j].y = __shfl_sync(FULL, v1.y, 6 + j);
        }
        #pragma unroll
        for (int hh = 0; hh < 2; ++hh) {
            int h = ln + hh * 32;
            float2 p = ((h >> 5) & 1) ? a1[0] : a0[0];
            #pragma unroll
            for (int j = 1; j < 6; ++j)
                p = cmul(p, ((h >> (5 - j)) & 1) ? a1[j] : a0[j]);
            if (hh == 0) R0 = p; else R1 = p;
        }
    }

    // ---------- Phase C: stores ----------
    // Lane ln's float4 quad covers R indices lo..lo+3 (invariant across iterations):
    //   lo = ((it*32+ln)*4) & 63 = (ln*4) & 63
    const int lo  = (ln << 2) & 63;
    const int sel = lo >> 5;
    const int sb  = lo & 31;
    float2 rq[4];
    #pragma unroll
    for (int k = 0; k < 4; ++k) {
        float x0 = __shfl_sync(FULL, R0.x, sb + k);
        float x1 = __shfl_sync(FULL, R1.x, sb + k);
        float y0 = __shfl_sync(FULL, R0.y, sb + k);
        float y1 = __shfl_sync(FULL, R1.y, sb + k);
        rq[k].x = sel ? x1 : x0;
        rq[k].y = sel ? y1 : y0;
    }

    float4* o4 = reinterpret_cast<float4*>(out + (size_t)g * 4096);
    const int lhi = ln >> 4;   // 0 or 1: which of the two L indices this half-warp uses
    #pragma unroll
    for (int it = 0; it < 32; ++it) {
        int idx = it * 2 + lhi;            // L index, 0..63; reg known at compile time
        float Lx, Ly;
        if (it < 16) {
            Lx = __shfl_sync(FULL, L0.x, idx);
            Ly = __shfl_sync(FULL, L0.y, idx);
        } else {
            Lx = __shfl_sync(FULL, L1.x, idx - 32);
            Ly = __shfl_sync(FULL, L1.y, idx - 32);
        }
        float4 r;
        r.x = Lx * rq[0].x - Ly * rq[0].y;
        r.y = Lx * rq[1].x - Ly * rq[1].y;
        r.z = Lx * rq[2].x - Ly * rq[2].y;
        r.w = Lx * rq[3].x - Ly * rq[3].y;
        o4[it * 32 + ln] = r;
    }
}

extern "C" void kernel_launch(void* const* d_in, const int* in_sizes, int n_in,
                              void* d_out, int out_size) {
    const float* angles = (const float*)d_in[0];
    const float* tQ     = (const float*)d_in[1];
    const float* tK     = (const float*)d_in[2];
    const float* tV     = (const float*)d_in[3];
    float* out          = (float*)d_out;

    const int NQ = 12;
    const int BS = in_sizes[0] / NQ;          // B*S = 4096
    const int L  = in_sizes[1] / (NQ * 3);    // 4 layers

    const int n_items = 3 * BS;               // 12288 warp-items
    const int blocks  = n_items / 8;          // 8 warps per 256-thread block
    vqc_warp_kernel<<<blocks, 256>>>(angles, tQ, tK, tV, out, BS, L);
}